// round 16
// baseline (speedup 1.0000x reference)
#include <cuda_runtime.h>
#include <cuda_fp16.h>
#include <math.h>
#include <float.h>
#include <stdint.h>

#define BB 32768
#define DD 256
#define KK 4096
#define GRID1 296          // 2 CTAs x 148 SMs, single wave
#define POOLW 128          // per-row pool: 8 cg x 8 threads x top-2 (packed u32)

// ---- scratch (static device globals: allocation-free) ----
__device__ float          g_wsq[KK];
__device__ unsigned int   g_counts[KK];
__device__ double         g_loss;
__device__ unsigned int   g_done;
__device__ __half         g_w16[KK * DD];        // f16(w * 4096)
__device__ unsigned int   g_pool[BB * POOLW];    // ordkey<<16 | (4095-idx)

// ---------------- helpers ----------------
__device__ __forceinline__ uint32_t smem_u32(const void* p) {
    return (uint32_t)__cvta_generic_to_shared(p);
}
__device__ __forceinline__ void cp16(uint32_t dst, const void* src) {
    asm volatile("cp.async.cg.shared.global [%0], [%1], 16;" :: "r"(dst), "l"(src));
}
__device__ __forceinline__ void cp_commit() {
    asm volatile("cp.async.commit_group;" ::: "memory");
}
template <int N> __device__ __forceinline__ void cp_wait() {
    asm volatile("cp.async.wait_group %0;" :: "n"(N) : "memory");
}
__device__ __forceinline__ uint32_t swz(uint32_t off) {
    return off ^ ((off >> 3) & 0x70);
}
__device__ __forceinline__ void ldsm4(uint32_t* r, uint32_t addr) {
    asm volatile("ldmatrix.sync.aligned.m8n8.x4.shared.b16 {%0,%1,%2,%3}, [%4];"
                 : "=r"(r[0]), "=r"(r[1]), "=r"(r[2]), "=r"(r[3]) : "r"(addr));
}
// f16 inputs, f16 accumulators (2 regs)
__device__ __forceinline__ void mma16816h(uint32_t* c, const uint32_t* a,
                                          const uint32_t* b) {
    asm volatile(
        "mma.sync.aligned.m16n8k16.row.col.f16.f16.f16.f16 "
        "{%0,%1}, {%2,%3,%4,%5}, {%6,%7}, {%0,%1};"
        : "+r"(c[0]), "+r"(c[1])
        : "r"(a[0]), "r"(a[1]), "r"(a[2]), "r"(a[3]), "r"(b[0]), "r"(b[1]));
}
// pack: monotone u32 key. high16 = sign-folded f16 (order-preserving),
// low16 = 4095-idx  =>  u32 max == (val desc, idx asc) — identical tie-break.
__device__ __forceinline__ uint32_t pack_cv(float v, int idx) {
    uint32_t h = (uint32_t)__half_as_ushort(__float2half_rn(v));
    uint32_t ord = (h & 0x8000u) ? (~h & 0xffffu) : (h | 0x8000u);
    return (ord << 16) | (uint32_t)(4095 - idx);
}
// exact inverse of the sign-fold: recover the f16 value from key high bits
__device__ __forceinline__ float unpack_val(uint32_t key) {
    uint32_t ord = key >> 16;
    uint16_t h = (ord & 0x8000u) ? (uint16_t)(ord ^ 0x8000u)
                                 : (uint16_t)(~ord);
    return __half2float(__ushort_as_half(h));
}

// ---------------- pass-1 smem layout (bytes) ----------------
// z f16: 4 slices x [128 rows x 64 f16] = 65536 ; w ring: 3 x 16384 = 49152
#define ZH_OFF    0u
#define W_OFF     65536u
#define SMEM_BYTES 114688u    // 112 KB/CTA; 2 CTAs = 224 KB <= 228 KB/SM

// ---------------------------------------------------------------------------
// Kernel A: codebook -> f16 (scaled by 4096), fp32 norms, zero accumulators.
// ---------------------------------------------------------------------------
__global__ void conv_w(const float* __restrict__ cb) {
    int r = blockIdx.x * 8 + (threadIdx.x >> 5);
    int lane = threadIdx.x & 31;
    const float* wr = cb + (size_t)r * DD + lane * 8;
    float4 a = *(const float4*)wr;
    float4 b = *(const float4*)(wr + 4);
    float s = a.x * a.x + a.y * a.y + a.z * a.z + a.w * a.w +
              b.x * b.x + b.y * b.y + b.z * b.z + b.w * b.w;
    const float sc = 4096.f;
    __half2 h0 = __float22half2_rn(make_float2(a.x * sc, a.y * sc));
    __half2 h1 = __float22half2_rn(make_float2(a.z * sc, a.w * sc));
    __half2 h2 = __float22half2_rn(make_float2(b.x * sc, b.y * sc));
    __half2 h3 = __float22half2_rn(make_float2(b.z * sc, b.w * sc));
    uint4 pk;
    pk.x = *(uint32_t*)&h0; pk.y = *(uint32_t*)&h1;
    pk.z = *(uint32_t*)&h2; pk.w = *(uint32_t*)&h3;
    *(uint4*)(g_w16 + (size_t)r * DD + lane * 8) = pk;
    #pragma unroll
    for (int o = 16; o > 0; o >>= 1) s += __shfl_xor_sync(0xffffffffu, s, o);
    if (lane == 0) { g_wsq[r] = s; g_counts[r] = 0u; }
    if (r == 0 && lane == 0) { g_loss = 0.0; g_done = 0u; }
}

// ---------------------------------------------------------------------------
// w-slice loader for absolute slice a into ring slot a%3.
// ---------------------------------------------------------------------------
__device__ __forceinline__ void load_wslice(int a, uint32_t sb, int tid) {
    const int ch = (a >> 2) & 31, s = a & 3;
    const uint32_t base = sb + W_OFF + (uint32_t)((a % 3) * 16384);
    #pragma unroll
    for (int i = 0; i < 4; ++i) {
        int flat = i * 256 + tid;        // 1024 16B-chunks
        int n = flat >> 3, c = flat & 7;
        uint32_t off = swz((uint32_t)(n * 128 + c * 16));
        cp16(base + off, g_w16 + (size_t)(ch * 128 + n) * DD + s * 64 + c * 8);
    }
}

// ---------------------------------------------------------------------------
// z staging: rows [row0, row0+128) fp32 -> f16 swizzled smem (plain stores).
// ---------------------------------------------------------------------------
__device__ __forceinline__ void stage_z(const float* __restrict__ z, int row0,
                                        char* smem, int tid) {
    #pragma unroll
    for (int i = 0; i < 32; ++i) {
        int flat = i * 256 + tid;            // 8192 float4
        int r = flat >> 6, d4 = flat & 63;
        float4 v = *(const float4*)(z + (size_t)(row0 + r) * DD + d4 * 4);
        __half2 p0 = __float22half2_rn(make_float2(v.x, v.y));
        __half2 p1 = __float22half2_rn(make_float2(v.z, v.w));
        uint2 pk;
        pk.x = *(uint32_t*)&p0; pk.y = *(uint32_t*)&p1;
        uint32_t off = swz((uint32_t)((d4 >> 4) * 16384 + r * 128 + (d4 & 15) * 8));
        *(uint2*)(smem + ZH_OFF + off) = pk;
    }
}

// ---------------------------------------------------------------------------
// Pass 1 (balanced, single-sync triple-buffered): identical to round 15.
// ---------------------------------------------------------------------------
__global__ void __launch_bounds__(256, 2)
vq_pass1(const float* __restrict__ z) {
    extern __shared__ __align__(1024) char smem[];
    const uint32_t sb = smem_u32(smem);
    const int tid = threadIdx.x;
    const int lane = tid & 31;
    const int warp = tid >> 5;
    const int wm = warp >> 1;        // 0..3 (M)
    const int wn = warp & 1;         // 0..1 (N)
    const int g = lane >> 3;
    const int l7 = lane & 7;

    // static unit range: [cta*256/37, (cta+1)*256/37) ; 296*256 = 37*2048
    const int u0 = (blockIdx.x * 256) / 37;
    const int u1 = ((blockIdx.x + 1) * 256) / 37;
    const int A0 = u0 * 16, A1 = u1 * 16;    // absolute slice indices

    load_wslice(A0, sb, tid); cp_commit();
    load_wslice(A0 + 1, sb, tid); cp_commit();

    int cur_rb = -1;
    int row0 = 0;

    float b0v[4], b1v[4];
    int   b0i[4], b1i[4];
    #pragma unroll
    for (int i = 0; i < 4; ++i) {
        b0v[i] = -FLT_MAX; b1v[i] = -FLT_MAX; b0i[i] = 0; b1i[i] = 0;
    }

    uint32_t acc[2][8][2];   // f16x2 accumulators

    for (int a = A0; a < A1; ++a) {
        const int rb = a >> 7, ch = (a >> 2) & 31, s = a & 3;

        if (rb != cur_rb) {              // new row-block: restage z
            __syncthreads();             // prior ldsm readers of z done
            cur_rb = rb;
            row0 = rb * 128;
            stage_z(z, row0, smem, tid);
        }

        // single per-slice barrier: prev slice's ldsm (w ring + z) complete
        __syncthreads();

        // refill ring slot (a+2)%3 — its readers (slice a-1) are done
        if (a + 2 < A1) load_wslice(a + 2, sb, tid);
        cp_commit();                     // empty group at tail keeps count
        cp_wait<2>();                    // slice a resident (2 in flight)

        if (s == 0) {
            #pragma unroll
            for (int mf = 0; mf < 2; ++mf)
                #pragma unroll
                for (int nf = 0; nf < 8; ++nf) {
                    acc[mf][nf][0] = 0u; acc[mf][nf][1] = 0u;
                }
        }

        const uint32_t wbase = sb + W_OFF + (uint32_t)((a % 3) * 16384);
        #pragma unroll
        for (int ks = 0; ks < 4; ++ks) {
            uint32_t ah[2][4];
            #pragma unroll
            for (int mf = 0; mf < 2; ++mf) {
                uint32_t off = (uint32_t)((wm * 32 + mf * 16 + (g & 1) * 8 + l7) * 128
                                          + ks * 32 + ((g >> 1) << 4));
                ldsm4(ah[mf], sb + ZH_OFF + swz(off) + (uint32_t)(s * 16384));
            }
            uint32_t bh[4][4];
            #pragma unroll
            for (int p = 0; p < 4; ++p) {
                uint32_t off = (uint32_t)((wn * 64 + p * 16 + ((g >> 1) << 3) + l7) * 128
                                          + ks * 32 + ((g & 1) << 4));
                ldsm4(bh[p], wbase + swz(off));
            }
            #pragma unroll
            for (int mf = 0; mf < 2; ++mf)
                #pragma unroll
                for (int p = 0; p < 4; ++p) {
                    mma16816h(acc[mf][2 * p],     ah[mf], &bh[p][0]);
                    mma16816h(acc[mf][2 * p + 1], ah[mf], &bh[p][2]);
                }
        }

        if (s == 3) {
            // update per-(thread,row-slot) top-2 over this chunk-group cell
            #pragma unroll
            for (int nf = 0; nf < 8; ++nf) {
                int col0 = ch * 128 + wn * 64 + nf * 8 + (lane & 3) * 2;
                #pragma unroll
                for (int mf = 0; mf < 2; ++mf) {
                    float2 p01 = __half22float2(*(__half2*)&acc[mf][nf][0]);
                    float2 p23 = __half22float2(*(__half2*)&acc[mf][nf][1]);
                    float vq[4] = {p01.x, p01.y, p23.x, p23.y};
                    #pragma unroll
                    for (int q = 0; q < 4; ++q) {
                        int sl = mf * 2 + (q >> 1);
                        float v = vq[q];
                        int c = col0 + (q & 1);
                        if (v > b1v[sl]) {
                            if (v > b0v[sl]) {
                                b1v[sl] = b0v[sl]; b1i[sl] = b0i[sl];
                                b0v[sl] = v;       b0i[sl] = c;
                            } else { b1v[sl] = v; b1i[sl] = c; }
                        }
                    }
                }
            }
            if ((a & 15) == 15) {
                // flush chunk-group pool: 2 packed keys per (thread,row-slot)
                int cg = (a >> 4) & 7;
                #pragma unroll
                for (int sl = 0; sl < 4; ++sl) {
                    int r = row0 + wm * 32 + (sl >> 1) * 16 + (sl & 1) * 8
                            + (lane >> 2);
                    int base = r * POOLW + cg * 16 + (wn * 4 + (lane & 3)) * 2;
                    uint2 pk;
                    pk.x = pack_cv(b0v[sl], b0i[sl]);
                    pk.y = pack_cv(b1v[sl], b1i[sl]);
                    *(uint2*)(g_pool + base) = pk;
                    b0v[sl] = -FLT_MAX; b1v[sl] = -FLT_MAX;
                    b0i[sl] = 0; b1i[sl] = 0;
                }
            }
        }
    }
}

// ---------------------------------------------------------------------------
// Pass 2 (fused output + final): top-4 by u32-max over the monotone packed
// 128-pool; warp-uniform approx-distance pruning (threshold 2e-4 ≈ 10σ of
// the f16-approx vs exact-fp32 discrepancy) selects which candidates get the
// exact fp32 rescore (reference rounding fl(fl(zsq+wsq)-2*dot), first-index
// tie-break, fma/shfl orders byte-identical to rounds 3-15 for every
// rescored candidate). z_q from winner registers; last block computes scalars.
// ---------------------------------------------------------------------------
__global__ void __launch_bounds__(256)
vq_rescore(const float* __restrict__ z, const float* __restrict__ cb,
           float* __restrict__ out, int out_size) {
    const int lane = threadIdx.x & 31;
    const int row = blockIdx.x * 8 + (threadIdx.x >> 5);

    // z row: 8 dims per lane
    float zr[8];
    {
        float4 a = *(const float4*)(z + (size_t)row * DD + lane * 8);
        float4 b = *(const float4*)(z + (size_t)row * DD + lane * 8 + 4);
        zr[0] = a.x; zr[1] = a.y; zr[2] = a.z; zr[3] = a.w;
        zr[4] = b.x; zr[5] = b.y; zr[6] = b.z; zr[7] = b.w;
    }
    float zsq = 0.f;
    #pragma unroll
    for (int k = 0; k < 8; ++k) zsq += zr[k] * zr[k];
    #pragma unroll
    for (int o = 16; o > 0; o >>= 1) zsq += __shfl_xor_sync(0xffffffffu, zsq, o);

    // pool: 4 packed keys per lane
    uint32_t key[4];
    {
        uint4 pv = *(const uint4*)(g_pool + row * POOLW + lane * 4);
        key[0] = pv.x; key[1] = pv.y; key[2] = pv.z; key[3] = pv.w;
    }

    // select top-4 candidates by u32 max (monotone key); keep key for decode
    int cand[4];
    uint32_t mkey[4];
    #pragma unroll
    for (int t = 0; t < 4; ++t) {
        uint32_t m = max(max(key[0], key[1]), max(key[2], key[3]));
        #pragma unroll
        for (int o = 16; o > 0; o >>= 1) {
            uint32_t mv = __shfl_xor_sync(0xffffffffu, m, o);
            m = max(m, mv);
        }
        mkey[t] = m;
        cand[t] = 4095 - (int)(m & 0xffffu);
        #pragma unroll
        for (int j = 0; j < 4; ++j)
            if (key[j] == m) key[j] = 0u;      // consume (0 < any real key)
    }

    // warp-uniform approx distances from the packed f16 dots (scaled by 4096)
    float ad[4], wsqv[4];
    float admin = FLT_MAX;
    #pragma unroll
    for (int t = 0; t < 4; ++t) {
        wsqv[t] = __ldg(&g_wsq[cand[t]]);
        float vdec = unpack_val(mkey[t]) * (1.f / 4096.f);
        ad[t] = (zsq + wsqv[t]) - 2.f * vdec;
        admin = fminf(admin, ad[t]);
    }

    // exact fp32 rescore of surviving candidates (same numerics as always)
    float bdist = FLT_MAX;
    int   widx = 0x7fffffff;
    float4 oa = make_float4(0.f, 0.f, 0.f, 0.f);
    float4 ob = make_float4(0.f, 0.f, 0.f, 0.f);
    #pragma unroll
    for (int t = 0; t < 4; ++t) {
        if (ad[t] <= admin + 2e-4f) {          // warp-uniform predicate
            const float* wp = cb + (size_t)cand[t] * DD + lane * 8;
            float4 wa = *(const float4*)wp;
            float4 wb = *(const float4*)(wp + 4);
            float d = 0.f;
            d = fmaf(zr[0], wa.x, d); d = fmaf(zr[1], wa.y, d);
            d = fmaf(zr[2], wa.z, d); d = fmaf(zr[3], wa.w, d);
            d = fmaf(zr[4], wb.x, d); d = fmaf(zr[5], wb.y, d);
            d = fmaf(zr[6], wb.z, d); d = fmaf(zr[7], wb.w, d);
            #pragma unroll
            for (int o = 16; o > 0; o >>= 1)
                d += __shfl_xor_sync(0xffffffffu, d, o);
            float dist = (zsq + wsqv[t]) - 2.f * d;
            if (dist < bdist || (dist == bdist && cand[t] < widx)) {
                bdist = dist; widx = cand[t]; oa = wa; ob = wb;
            }
        }
    }

    float lsum = 0.f;
    {
        float* op = out + (size_t)row * DD + lane * 8;
        if ((row + 1) * DD <= out_size) {
            *(float4*)op = oa;
            *(float4*)(op + 4) = ob;
        }
        float w8[8] = {oa.x, oa.y, oa.z, oa.w, ob.x, ob.y, ob.z, ob.w};
        #pragma unroll
        for (int k = 0; k < 8; ++k) {
            float dd = w8[k] - zr[k];
            lsum += dd * dd;
        }
    }
    #pragma unroll
    for (int o = 16; o > 0; o >>= 1) lsum += __shfl_xor_sync(0xffffffffu, lsum, o);

    if (lane == 0) {
        atomicAdd(&g_counts[widx], 1u);
        atomicAdd(&g_loss, (double)lsum);
        int pos = BB * DD + row;
        if (pos < out_size) out[pos] = (float)widx;
        __threadfence();
    }

    // ---- fused finalization: last block computes scalars ----
    __shared__ int slast;
    __shared__ double red[8];
    __syncthreads();
    if (threadIdx.x == 0)
        slast = (atomicAdd(&g_done, 1u) == (unsigned)(gridDim.x - 1)) ? 1 : 0;
    __syncthreads();
    if (slast) {
        int t = threadIdx.x;
        double s = 0.0;
        for (int k = t; k < KK; k += 256) {
            unsigned c = atomicAdd(&g_counts[k], 0u);   // coherent read
            float p = (float)c / (float)BB;
            s += (double)(p * logf(p + 1e-10f));
        }
        #pragma unroll
        for (int o = 16; o > 0; o >>= 1) s += __shfl_xor_sync(0xffffffffu, s, o);
        if ((t & 31) == 0) red[t >> 5] = s;
        __syncthreads();
        if (t < 32) {
            double vv = (t < 8) ? red[t] : 0.0;
            #pragma unroll
            for (int o = 4; o > 0; o >>= 1) vv += __shfl_xor_sync(0xffffffffu, vv, o);
            if (t == 0) {
                double loss = atomicAdd(&g_loss, 0.0);  // coherent read
                int p0 = BB * DD + BB;
                if (p0 < out_size)
                    out[p0] = (float)(loss / ((double)BB * (double)DD) * 1.25);
                if (p0 + 1 < out_size)
                    out[p0 + 1] = expf((float)(-vv));
            }
        }
    }
}

// ---------------------------------------------------------------------------
extern "C" void kernel_launch(void* const* d_in, const int* in_sizes, int n_in,
                              void* d_out, int out_size) {
    const float* z  = (const float*)d_in[0];   // z_e [32768, 256] f32
    const float* cb = (const float*)d_in[1];   // codebook [4096, 256] f32
    float* out = (float*)d_out;

    cudaFuncSetAttribute(vq_pass1,
                         cudaFuncAttributeMaxDynamicSharedMemorySize, SMEM_BYTES);

    conv_w<<<KK / 8, 256>>>(cb);
    vq_pass1<<<GRID1, 256, SMEM_BYTES>>>(z);
    vq_rescore<<<BB / 8, 256>>>(z, cb, out, out_size);
}

// round 17
// speedup vs baseline: 1.0091x; 1.0091x over previous
#include <cuda_runtime.h>
#include <cuda_fp16.h>
#include <math.h>
#include <float.h>
#include <stdint.h>

#define BB 32768
#define DD 256
#define KK 4096
#define GRID1 296          // 2 CTAs x 148 SMs, single wave
#define POOLW 128          // per-row pool: 8 cg x 8 threads x top-2 (packed u32)

// ---- scratch (static device globals: allocation-free) ----
__device__ float          g_wsq[KK];
__device__ unsigned int   g_counts[KK];
__device__ double         g_loss;
__device__ unsigned int   g_done;
__device__ __half         g_w16[KK * DD];        // f16(w * 4096)
__device__ unsigned int   g_pool[BB * POOLW];    // ordkey<<16 | (4095-idx)

// ---------------- helpers ----------------
__device__ __forceinline__ uint32_t smem_u32(const void* p) {
    return (uint32_t)__cvta_generic_to_shared(p);
}
__device__ __forceinline__ void cp16(uint32_t dst, const void* src) {
    asm volatile("cp.async.cg.shared.global [%0], [%1], 16;" :: "r"(dst), "l"(src));
}
__device__ __forceinline__ void cp_commit() {
    asm volatile("cp.async.commit_group;" ::: "memory");
}
template <int N> __device__ __forceinline__ void cp_wait() {
    asm volatile("cp.async.wait_group %0;" :: "n"(N) : "memory");
}
__device__ __forceinline__ uint32_t swz(uint32_t off) {
    return off ^ ((off >> 3) & 0x70);
}
__device__ __forceinline__ void ldsm4(uint32_t* r, uint32_t addr) {
    asm volatile("ldmatrix.sync.aligned.m8n8.x4.shared.b16 {%0,%1,%2,%3}, [%4];"
                 : "=r"(r[0]), "=r"(r[1]), "=r"(r[2]), "=r"(r[3]) : "r"(addr));
}
// f16 inputs, f16 accumulators (2 regs)
__device__ __forceinline__ void mma16816h(uint32_t* c, const uint32_t* a,
                                          const uint32_t* b) {
    asm volatile(
        "mma.sync.aligned.m16n8k16.row.col.f16.f16.f16.f16 "
        "{%0,%1}, {%2,%3,%4,%5}, {%6,%7}, {%0,%1};"
        : "+r"(c[0]), "+r"(c[1])
        : "r"(a[0]), "r"(a[1]), "r"(a[2]), "r"(a[3]), "r"(b[0]), "r"(b[1]));
}
// pack: monotone u32 key. high16 = sign-folded f16 (order-preserving),
// low16 = 4095-idx  =>  u32 max == (val desc, idx asc) — identical tie-break.
__device__ __forceinline__ uint32_t pack_cv(float v, int idx) {
    uint32_t h = (uint32_t)__half_as_ushort(__float2half_rn(v));
    uint32_t ord = (h & 0x8000u) ? (~h & 0xffffu) : (h | 0x8000u);
    return (ord << 16) | (uint32_t)(4095 - idx);
}
// exact inverse of the sign-fold: recover the f16 value from key high bits
__device__ __forceinline__ float unpack_val(uint32_t key) {
    uint32_t ord = key >> 16;
    uint16_t h = (ord & 0x8000u) ? (uint16_t)(ord ^ 0x8000u)
                                 : (uint16_t)(~ord);
    return __half2float(__ushort_as_half(h));
}

// ---------------- pass-1 smem layout (bytes) ----------------
// z f16: 4 slices x [128 rows x 64 f16] = 65536 ; w ring: 3 x 16384 = 49152
#define ZH_OFF    0u
#define W_OFF     65536u
#define SMEM_BYTES 114688u    // 112 KB/CTA; 2 CTAs = 224 KB <= 228 KB/SM

// ---------------------------------------------------------------------------
// Kernel A: codebook -> f16 (scaled by 4096), fp32 norms, zero accumulators.
// ---------------------------------------------------------------------------
__global__ void conv_w(const float* __restrict__ cb) {
    int r = blockIdx.x * 8 + (threadIdx.x >> 5);
    int lane = threadIdx.x & 31;
    const float* wr = cb + (size_t)r * DD + lane * 8;
    float4 a = *(const float4*)wr;
    float4 b = *(const float4*)(wr + 4);
    float s = a.x * a.x + a.y * a.y + a.z * a.z + a.w * a.w +
              b.x * b.x + b.y * b.y + b.z * b.z + b.w * b.w;
    const float sc = 4096.f;
    __half2 h0 = __float22half2_rn(make_float2(a.x * sc, a.y * sc));
    __half2 h1 = __float22half2_rn(make_float2(a.z * sc, a.w * sc));
    __half2 h2 = __float22half2_rn(make_float2(b.x * sc, b.y * sc));
    __half2 h3 = __float22half2_rn(make_float2(b.z * sc, b.w * sc));
    uint4 pk;
    pk.x = *(uint32_t*)&h0; pk.y = *(uint32_t*)&h1;
    pk.z = *(uint32_t*)&h2; pk.w = *(uint32_t*)&h3;
    *(uint4*)(g_w16 + (size_t)r * DD + lane * 8) = pk;
    #pragma unroll
    for (int o = 16; o > 0; o >>= 1) s += __shfl_xor_sync(0xffffffffu, s, o);
    if (lane == 0) { g_wsq[r] = s; g_counts[r] = 0u; }
    if (r == 0 && lane == 0) { g_loss = 0.0; g_done = 0u; }
}

// ---------------------------------------------------------------------------
// w-slice loader for absolute slice a into ring slot a%3.
// ---------------------------------------------------------------------------
__device__ __forceinline__ void load_wslice(int a, uint32_t sb, int tid) {
    const int ch = (a >> 2) & 31, s = a & 3;
    const uint32_t base = sb + W_OFF + (uint32_t)((a % 3) * 16384);
    #pragma unroll
    for (int i = 0; i < 4; ++i) {
        int flat = i * 256 + tid;        // 1024 16B-chunks
        int n = flat >> 3, c = flat & 7;
        uint32_t off = swz((uint32_t)(n * 128 + c * 16));
        cp16(base + off, g_w16 + (size_t)(ch * 128 + n) * DD + s * 64 + c * 8);
    }
}

// ---------------------------------------------------------------------------
// z staging: rows [row0, row0+128) fp32 -> f16 swizzled smem (plain stores).
// ---------------------------------------------------------------------------
__device__ __forceinline__ void stage_z(const float* __restrict__ z, int row0,
                                        char* smem, int tid) {
    #pragma unroll
    for (int i = 0; i < 32; ++i) {
        int flat = i * 256 + tid;            // 8192 float4
        int r = flat >> 6, d4 = flat & 63;
        float4 v = *(const float4*)(z + (size_t)(row0 + r) * DD + d4 * 4);
        __half2 p0 = __float22half2_rn(make_float2(v.x, v.y));
        __half2 p1 = __float22half2_rn(make_float2(v.z, v.w));
        uint2 pk;
        pk.x = *(uint32_t*)&p0; pk.y = *(uint32_t*)&p1;
        uint32_t off = swz((uint32_t)((d4 >> 4) * 16384 + r * 128 + (d4 & 15) * 8));
        *(uint2*)(smem + ZH_OFF + off) = pk;
    }
}

// ---------------------------------------------------------------------------
// Pass 1 (balanced, single-sync triple-buffered): identical to round 15.
// ---------------------------------------------------------------------------
__global__ void __launch_bounds__(256, 2)
vq_pass1(const float* __restrict__ z) {
    extern __shared__ __align__(1024) char smem[];
    const uint32_t sb = smem_u32(smem);
    const int tid = threadIdx.x;
    const int lane = tid & 31;
    const int warp = tid >> 5;
    const int wm = warp >> 1;        // 0..3 (M)
    const int wn = warp & 1;         // 0..1 (N)
    const int g = lane >> 3;
    const int l7 = lane & 7;

    // static unit range: [cta*256/37, (cta+1)*256/37) ; 296*256 = 37*2048
    const int u0 = (blockIdx.x * 256) / 37;
    const int u1 = ((blockIdx.x + 1) * 256) / 37;
    const int A0 = u0 * 16, A1 = u1 * 16;    // absolute slice indices

    load_wslice(A0, sb, tid); cp_commit();
    load_wslice(A0 + 1, sb, tid); cp_commit();

    int cur_rb = -1;
    int row0 = 0;

    float b0v[4], b1v[4];
    int   b0i[4], b1i[4];
    #pragma unroll
    for (int i = 0; i < 4; ++i) {
        b0v[i] = -FLT_MAX; b1v[i] = -FLT_MAX; b0i[i] = 0; b1i[i] = 0;
    }

    uint32_t acc[2][8][2];   // f16x2 accumulators

    for (int a = A0; a < A1; ++a) {
        const int rb = a >> 7, ch = (a >> 2) & 31, s = a & 3;

        if (rb != cur_rb) {              // new row-block: restage z
            __syncthreads();             // prior ldsm readers of z done
            cur_rb = rb;
            row0 = rb * 128;
            stage_z(z, row0, smem, tid);
        }

        // single per-slice barrier: prev slice's ldsm (w ring + z) complete
        __syncthreads();

        // refill ring slot (a+2)%3 — its readers (slice a-1) are done
        if (a + 2 < A1) load_wslice(a + 2, sb, tid);
        cp_commit();                     // empty group at tail keeps count
        cp_wait<2>();                    // slice a resident (2 in flight)

        if (s == 0) {
            #pragma unroll
            for (int mf = 0; mf < 2; ++mf)
                #pragma unroll
                for (int nf = 0; nf < 8; ++nf) {
                    acc[mf][nf][0] = 0u; acc[mf][nf][1] = 0u;
                }
        }

        const uint32_t wbase = sb + W_OFF + (uint32_t)((a % 3) * 16384);
        #pragma unroll
        for (int ks = 0; ks < 4; ++ks) {
            uint32_t ah[2][4];
            #pragma unroll
            for (int mf = 0; mf < 2; ++mf) {
                uint32_t off = (uint32_t)((wm * 32 + mf * 16 + (g & 1) * 8 + l7) * 128
                                          + ks * 32 + ((g >> 1) << 4));
                ldsm4(ah[mf], sb + ZH_OFF + swz(off) + (uint32_t)(s * 16384));
            }
            uint32_t bh[4][4];
            #pragma unroll
            for (int p = 0; p < 4; ++p) {
                uint32_t off = (uint32_t)((wn * 64 + p * 16 + ((g >> 1) << 3) + l7) * 128
                                          + ks * 32 + ((g & 1) << 4));
                ldsm4(bh[p], wbase + swz(off));
            }
            #pragma unroll
            for (int mf = 0; mf < 2; ++mf)
                #pragma unroll
                for (int p = 0; p < 4; ++p) {
                    mma16816h(acc[mf][2 * p],     ah[mf], &bh[p][0]);
                    mma16816h(acc[mf][2 * p + 1], ah[mf], &bh[p][2]);
                }
        }

        if (s == 3) {
            // update per-(thread,row-slot) top-2 over this chunk-group cell
            #pragma unroll
            for (int nf = 0; nf < 8; ++nf) {
                int col0 = ch * 128 + wn * 64 + nf * 8 + (lane & 3) * 2;
                #pragma unroll
                for (int mf = 0; mf < 2; ++mf) {
                    float2 p01 = __half22float2(*(__half2*)&acc[mf][nf][0]);
                    float2 p23 = __half22float2(*(__half2*)&acc[mf][nf][1]);
                    float vq[4] = {p01.x, p01.y, p23.x, p23.y};
                    #pragma unroll
                    for (int q = 0; q < 4; ++q) {
                        int sl = mf * 2 + (q >> 1);
                        float v = vq[q];
                        int c = col0 + (q & 1);
                        if (v > b1v[sl]) {
                            if (v > b0v[sl]) {
                                b1v[sl] = b0v[sl]; b1i[sl] = b0i[sl];
                                b0v[sl] = v;       b0i[sl] = c;
                            } else { b1v[sl] = v; b1i[sl] = c; }
                        }
                    }
                }
            }
            if ((a & 15) == 15) {
                // flush chunk-group pool: 2 packed keys per (thread,row-slot)
                int cg = (a >> 4) & 7;
                #pragma unroll
                for (int sl = 0; sl < 4; ++sl) {
                    int r = row0 + wm * 32 + (sl >> 1) * 16 + (sl & 1) * 8
                            + (lane >> 2);
                    int base = r * POOLW + cg * 16 + (wn * 4 + (lane & 3)) * 2;
                    uint2 pk;
                    pk.x = pack_cv(b0v[sl], b0i[sl]);
                    pk.y = pack_cv(b1v[sl], b1i[sl]);
                    *(uint2*)(g_pool + base) = pk;
                    b0v[sl] = -FLT_MAX; b1v[sl] = -FLT_MAX;
                    b0i[sl] = 0; b1i[sl] = 0;
                }
            }
        }
    }
}

// ---------------------------------------------------------------------------
// Pass 2 (fused output + final): top-4 by u32-max over the monotone packed
// 128-pool (streaming __ldcs — read once); warp-uniform approx-distance
// pruning (2e-4 ≈ 10σ) selects candidates for the exact fp32 rescore
// (reference rounding fl(fl(zsq+wsq)-2*dot), first-index tie-break, fma/shfl
// orders byte-identical to rounds 3-16). z_q written with streaming __stcs
// (never re-read). Last block computes scalars.
// ---------------------------------------------------------------------------
__global__ void __launch_bounds__(256)
vq_rescore(const float* __restrict__ z, const float* __restrict__ cb,
           float* __restrict__ out, int out_size) {
    const int lane = threadIdx.x & 31;
    const int row = blockIdx.x * 8 + (threadIdx.x >> 5);

    // z row: 8 dims per lane
    float zr[8];
    {
        float4 a = *(const float4*)(z + (size_t)row * DD + lane * 8);
        float4 b = *(const float4*)(z + (size_t)row * DD + lane * 8 + 4);
        zr[0] = a.x; zr[1] = a.y; zr[2] = a.z; zr[3] = a.w;
        zr[4] = b.x; zr[5] = b.y; zr[6] = b.z; zr[7] = b.w;
    }
    float zsq = 0.f;
    #pragma unroll
    for (int k = 0; k < 8; ++k) zsq += zr[k] * zr[k];
    #pragma unroll
    for (int o = 16; o > 0; o >>= 1) zsq += __shfl_xor_sync(0xffffffffu, zsq, o);

    // pool: 4 packed keys per lane (streaming load — read exactly once)
    uint32_t key[4];
    {
        uint4 pv = __ldcs((const uint4*)(g_pool + row * POOLW + lane * 4));
        key[0] = pv.x; key[1] = pv.y; key[2] = pv.z; key[3] = pv.w;
    }

    // select top-4 candidates by u32 max (monotone key); keep key for decode
    int cand[4];
    uint32_t mkey[4];
    #pragma unroll
    for (int t = 0; t < 4; ++t) {
        uint32_t m = max(max(key[0], key[1]), max(key[2], key[3]));
        #pragma unroll
        for (int o = 16; o > 0; o >>= 1) {
            uint32_t mv = __shfl_xor_sync(0xffffffffu, m, o);
            m = max(m, mv);
        }
        mkey[t] = m;
        cand[t] = 4095 - (int)(m & 0xffffu);
        #pragma unroll
        for (int j = 0; j < 4; ++j)
            if (key[j] == m) key[j] = 0u;      // consume (0 < any real key)
    }

    // warp-uniform approx distances from the packed f16 dots (scaled by 4096)
    float ad[4], wsqv[4];
    float admin = FLT_MAX;
    #pragma unroll
    for (int t = 0; t < 4; ++t) {
        wsqv[t] = __ldg(&g_wsq[cand[t]]);
        float vdec = unpack_val(mkey[t]) * (1.f / 4096.f);
        ad[t] = (zsq + wsqv[t]) - 2.f * vdec;
        admin = fminf(admin, ad[t]);
    }

    // exact fp32 rescore of surviving candidates (same numerics as always)
    float bdist = FLT_MAX;
    int   widx = 0x7fffffff;
    float4 oa = make_float4(0.f, 0.f, 0.f, 0.f);
    float4 ob = make_float4(0.f, 0.f, 0.f, 0.f);
    #pragma unroll
    for (int t = 0; t < 4; ++t) {
        if (ad[t] <= admin + 2e-4f) {          // warp-uniform predicate
            const float* wp = cb + (size_t)cand[t] * DD + lane * 8;
            float4 wa = *(const float4*)wp;
            float4 wb = *(const float4*)(wp + 4);
            float d = 0.f;
            d = fmaf(zr[0], wa.x, d); d = fmaf(zr[1], wa.y, d);
            d = fmaf(zr[2], wa.z, d); d = fmaf(zr[3], wa.w, d);
            d = fmaf(zr[4], wb.x, d); d = fmaf(zr[5], wb.y, d);
            d = fmaf(zr[6], wb.z, d); d = fmaf(zr[7], wb.w, d);
            #pragma unroll
            for (int o = 16; o > 0; o >>= 1)
                d += __shfl_xor_sync(0xffffffffu, d, o);
            float dist = (zsq + wsqv[t]) - 2.f * d;
            if (dist < bdist || (dist == bdist && cand[t] < widx)) {
                bdist = dist; widx = cand[t]; oa = wa; ob = wb;
            }
        }
    }

    float lsum = 0.f;
    {
        float* op = out + (size_t)row * DD + lane * 8;
        if ((row + 1) * DD <= out_size) {
            __stcs((float4*)op, oa);           // streaming: never re-read
            __stcs((float4*)(op + 4), ob);
        }
        float w8[8] = {oa.x, oa.y, oa.z, oa.w, ob.x, ob.y, ob.z, ob.w};
        #pragma unroll
        for (int k = 0; k < 8; ++k) {
            float dd = w8[k] - zr[k];
            lsum += dd * dd;
        }
    }
    #pragma unroll
    for (int o = 16; o > 0; o >>= 1) lsum += __shfl_xor_sync(0xffffffffu, lsum, o);

    if (lane == 0) {
        atomicAdd(&g_counts[widx], 1u);
        atomicAdd(&g_loss, (double)lsum);
        int pos = BB * DD + row;
        if (pos < out_size) out[pos] = (float)widx;
        __threadfence();
    }

    // ---- fused finalization: last block computes scalars ----
    __shared__ int slast;
    __shared__ double red[8];
    __syncthreads();
    if (threadIdx.x == 0)
        slast = (atomicAdd(&g_done, 1u) == (unsigned)(gridDim.x - 1)) ? 1 : 0;
    __syncthreads();
    if (slast) {
        int t = threadIdx.x;
        double s = 0.0;
        for (int k = t; k < KK; k += 256) {
            unsigned c = atomicAdd(&g_counts[k], 0u);   // coherent read
            float p = (float)c / (float)BB;
            s += (double)(p * logf(p + 1e-10f));
        }
        #pragma unroll
        for (int o = 16; o > 0; o >>= 1) s += __shfl_xor_sync(0xffffffffu, s, o);
        if ((t & 31) == 0) red[t >> 5] = s;
        __syncthreads();
        if (t < 32) {
            double vv = (t < 8) ? red[t] : 0.0;
            #pragma unroll
            for (int o = 4; o > 0; o >>= 1) vv += __shfl_xor_sync(0xffffffffu, vv, o);
            if (t == 0) {
                double loss = atomicAdd(&g_loss, 0.0);  // coherent read
                int p0 = BB * DD + BB;
                if (p0 < out_size)
                    out[p0] = (float)(loss / ((double)BB * (double)DD) * 1.25);
                if (p0 + 1 < out_size)
                    out[p0 + 1] = expf((float)(-vv));
            }
        }
    }
}

// ---------------------------------------------------------------------------
extern "C" void kernel_launch(void* const* d_in, const int* in_sizes, int n_in,
                              void* d_out, int out_size) {
    const float* z  = (const float*)d_in[0];   // z_e [32768, 256] f32
    const float* cb = (const float*)d_in[1];   // codebook [4096, 256] f32
    float* out = (float*)d_out;

    cudaFuncSetAttribute(vq_pass1,
                         cudaFuncAttributeMaxDynamicSharedMemorySize, SMEM_BYTES);

    conv_w<<<KK / 8, 256>>>(cb);
    vq_pass1<<<GRID1, 256, SMEM_BYTES>>>(z);
    vq_rescore<<<BB / 8, 256>>>(z, cb, out, out_size);
}